// round 14
// baseline (speedup 1.0000x reference)
#include <cuda_runtime.h>
#include <math.h>

// Problem dims (fixed)
#define BB 4
#define SS 1024
#define DM 512
#define HH 8
#define HDD 64
#define HIDD 2048
#define NT (BB*SS)                 // 4096 token rows
#define NDE ((size_t)NT*DM)        // 2097152
#define NHE ((size_t)NT*HIDD)      // 8388608
#define DDE ((size_t)DM*DM)        // 262144
#define GDE ((size_t)HIDD*DM)      // 1048576

typedef unsigned long long ull;
typedef unsigned int uint32;

// -------- scratch: one big __device__ array (no allocations allowed) --------
__device__ float g_scratch[96468992];

// ---- tf32 helpers ----
__device__ __forceinline__ uint32 to_tf32(float x) {
    uint32 r; asm("cvt.rna.tf32.f32 %0, %1;" : "=r"(r) : "f"(x)); return r;
}
#define MMA_TF32(d, a, b) \
    asm volatile("mma.sync.aligned.m16n8k8.row.col.f32.tf32.tf32.f32 " \
                 "{%0,%1,%2,%3}, {%4,%5,%6,%7}, {%8,%9}, {%0,%1,%2,%3};" \
                 : "+f"(d[0]), "+f"(d[1]), "+f"(d[2]), "+f"(d[3]) \
                 : "r"(a[0]), "r"(a[1]), "r"(a[2]), "r"(a[3]), "r"(b[0]), "r"(b[1]))

// ---------------------------------------------------------------------------
// all 7 magnitude/phase weight materializations in ONE launch
__global__ __launch_bounds__(256) void make_w_all_kernel(float* __restrict__ Sp,
    const float* __restrict__ q_lm, const float* __restrict__ q_ph,
    const float* __restrict__ k_lm, const float* __restrict__ k_ph,
    const float* __restrict__ v_lm, const float* __restrict__ v_ph,
    const float* __restrict__ o_lm, const float* __restrict__ o_ph,
    const float* __restrict__ g_lm, const float* __restrict__ g_ph,
    const float* __restrict__ u_lm, const float* __restrict__ u_ph,
    const float* __restrict__ d_lm, const float* __restrict__ d_ph) {
    int i = blockIdx.x * 256 + threadIdx.x;     // < 4*DDE + 3*GDE = 4194304
    const float *lm, *ph;
    float *wr, *wi;
    int off;
    if (i < (int)(4 * DDE)) {
        int w = i / (int)DDE; off = i - w * (int)DDE;
        lm = (w == 0) ? q_lm : (w == 1) ? k_lm : (w == 2) ? v_lm : o_lm;
        ph = (w == 0) ? q_ph : (w == 1) ? k_ph : (w == 2) ? v_ph : o_ph;
        wr = Sp + (size_t)w * 2 * DDE + off; wi = wr + DDE;
    } else {
        int j = i - (int)(4 * DDE);
        int w = j / (int)GDE; off = j - w * (int)GDE;
        lm = (w == 0) ? g_lm : (w == 1) ? u_lm : d_lm;
        ph = (w == 0) ? g_ph : (w == 1) ? u_ph : d_ph;
        wr = Sp + 8 * DDE + (size_t)w * 2 * GDE + off; wi = wr + GDE;
    }
    float m = expf(lm[off]);
    float p = ph[off];
    *wr = m * cosf(p);
    *wi = m * sinf(p);
}

// complex layernorm over last dim D=512; one block per row, 256 threads
__global__ __launch_bounds__(256) void cln_kernel(const float* __restrict__ xr,
                                                  const float* __restrict__ xi,
                                                  const float* __restrict__ gr,
                                                  const float* __restrict__ gi,
                                                  const float* __restrict__ br,
                                                  const float* __restrict__ bi,
                                                  float* __restrict__ outr,
                                                  float* __restrict__ outi) {
    int row = blockIdx.x;
    int t = threadIdx.x;
    const float* xrp = xr + (size_t)row * DM;
    const float* xip = xi + (size_t)row * DM;
    float a0 = xrp[t], a1 = xrp[t + 256];
    float b0 = xip[t], b1 = xip[t + 256];
    __shared__ float red[256];

    red[t] = a0 + a1; __syncthreads();
    for (int s2 = 128; s2 > 0; s2 >>= 1) { if (t < s2) red[t] += red[t + s2]; __syncthreads(); }
    float mr = red[0] * (1.0f / DM); __syncthreads();

    red[t] = b0 + b1; __syncthreads();
    for (int s2 = 128; s2 > 0; s2 >>= 1) { if (t < s2) red[t] += red[t + s2]; __syncthreads(); }
    float mi = red[0] * (1.0f / DM); __syncthreads();

    float c0 = a0 - mr, c1 = a1 - mr, d0 = b0 - mi, d1 = b1 - mi;
    red[t] = c0 * c0 + c1 * c1 + d0 * d0 + d1 * d1; __syncthreads();
    for (int s2 = 128; s2 > 0; s2 >>= 1) { if (t < s2) red[t] += red[t + s2]; __syncthreads(); }
    float inv = rsqrtf(red[0] * (1.0f / DM) + 1e-6f);

    float* orow = outr + (size_t)row * DM;
    float* oirow = outi + (size_t)row * DM;
    {
        float nr = c0 * inv, ni = d0 * inv;
        orow[t]  = nr * gr[t] - ni * gi[t] + br[t];
        oirow[t] = nr * gi[t] + ni * gr[t] + bi[t];
    }
    {
        int d_ = t + 256;
        float nr = c1 * inv, ni = d1 * inv;
        orow[d_]  = nr * gr[d_] - ni * gi[d_] + br[d_];
        oirow[d_] = nr * gi[d_] + ni * gr[d_] + bi[d_];
    }
}

// ============================================================================
// Tensor-core complex GEMM (tf32 mma.sync m16n8k8), batched over blockIdx.z.
// SMEM k-columns PERMUTED so each mma fragment pair (c, c+4) is adjacent:
//   pos(c) = (c>>3)*8 + (c&3)*2 + ((c&7)>>2)
// -> all fragment gathers become conflict-free LDS.64 (row pad 24 words).
// Arithmetic identical to the unpermuted version.
// mode 0: write acc+bias. mode 1: +X (fused residual). mode 3: += C.
// ============================================================================
__global__ __launch_bounds__(256, 2) void cgemm_tc_kernel(
    const float* __restrict__ Ar, const float* __restrict__ Ai,
    const float* __restrict__ Wbase, size_t wzs, size_t wioff,
    float* __restrict__ Cbase, size_t czs, size_t cioff,
    const float* __restrict__ bm0, const float* __restrict__ bp0,
    const float* __restrict__ bm1, const float* __restrict__ bp1,
    const float* __restrict__ bm2, const float* __restrict__ bp2,
    const float* __restrict__ Xr, const float* __restrict__ Xi,
    int mode, int M, int N, int K) {
    __shared__ uint32 sAr[128][24], sAi[128][24];
    __shared__ uint32 sWr[64][24],  sWi[64][24];

    int zz = blockIdx.z;
    const float* Wr = Wbase + (size_t)zz * wzs;
    const float* Wi = Wr + wioff;
    float* Cr = Cbase + (size_t)zz * czs;
    float* Ci = Cr + cioff;
    const float* bm = (zz == 0) ? bm0 : (zz == 1) ? bm1 : bm2;
    const float* bp = (zz == 0) ? bp0 : (zz == 1) ? bp1 : bp2;

    int m0 = blockIdx.y * 128, n0 = blockIdx.x * 64;
    int tid = threadIdx.x;
    int warp = tid >> 5, lane = tid & 31;
    int wm = warp & 3, wn = warp >> 2;
    int g = lane >> 2, t = lane & 3;

    // fill assignments
    int rA = tid >> 1;                 // 0..127
    int hA = tid & 1;                  // k-half (8 cols)
    int rW = tid >> 2;                 // 0..63
    int selW = (tid >> 1) & 1;         // 0=Wr, 1=Wi
    int hW = tid & 1;

    float accR[2][4][4], accI[2][4][4];
    #pragma unroll
    for (int mi = 0; mi < 2; mi++)
        #pragma unroll
        for (int ni = 0; ni < 4; ni++)
            #pragma unroll
            for (int e = 0; e < 4; e++) { accR[mi][ni][e] = 0.f; accI[mi][ni][e] = 0.f; }

    for (int k0 = 0; k0 < K; k0 += 16) {
        // ---- fill A (both r and i) with permuted columns ----
        {
            const float* arow = Ar + (size_t)(m0 + rA) * K + k0 + hA * 8;
            const float* brow = Ai + (size_t)(m0 + rA) * K + k0 + hA * 8;
            float4 va = *(const float4*)arow;        // cols +0..3
            float4 vb = *(const float4*)(arow + 4);  // cols +4..7
            uint32* dst = &sAr[rA][hA * 8];
            *(uint2*)(dst + 0) = make_uint2(to_tf32(va.x), to_tf32(vb.x));
            *(uint2*)(dst + 2) = make_uint2(to_tf32(va.y), to_tf32(vb.y));
            *(uint2*)(dst + 4) = make_uint2(to_tf32(va.z), to_tf32(vb.z));
            *(uint2*)(dst + 6) = make_uint2(to_tf32(va.w), to_tf32(vb.w));
            float4 vc = *(const float4*)brow;
            float4 vd = *(const float4*)(brow + 4);
            uint32* dsi = &sAi[rA][hA * 8];
            *(uint2*)(dsi + 0) = make_uint2(to_tf32(vc.x), to_tf32(vd.x));
            *(uint2*)(dsi + 2) = make_uint2(to_tf32(vc.y), to_tf32(vd.y));
            *(uint2*)(dsi + 4) = make_uint2(to_tf32(vc.z), to_tf32(vd.z));
            *(uint2*)(dsi + 6) = make_uint2(to_tf32(vc.w), to_tf32(vd.w));
        }
        // ---- fill W (r or i selected per thread) ----
        {
            const float* wsrc = (selW ? Wi : Wr) + (size_t)(n0 + rW) * K + k0 + hW * 8;
            float4 va = *(const float4*)wsrc;
            float4 vb = *(const float4*)(wsrc + 4);
            uint32* dst = (selW ? &sWi[rW][hW * 8] : &sWr[rW][hW * 8]);
            *(uint2*)(dst + 0) = make_uint2(to_tf32(va.x), to_tf32(vb.x));
            *(uint2*)(dst + 2) = make_uint2(to_tf32(va.y), to_tf32(vb.y));
            *(uint2*)(dst + 4) = make_uint2(to_tf32(va.z), to_tf32(vb.z));
            *(uint2*)(dst + 6) = make_uint2(to_tf32(va.w), to_tf32(vb.w));
        }
        __syncthreads();

        #pragma unroll
        for (int kk = 0; kk < 16; kk += 8) {
            int cb = (kk >> 3) * 8 + t * 2;
            uint2 fwrv[4], fwiv[4];
            #pragma unroll
            for (int ni = 0; ni < 4; ni++) {
                int n = wn * 32 + ni * 8 + g;
                fwrv[ni] = *(const uint2*)&sWr[n][cb];
                fwiv[ni] = *(const uint2*)&sWi[n][cb];
            }
            #pragma unroll
            for (int mi = 0; mi < 2; mi++) {
                int r = wm * 32 + mi * 16 + g;
                uint2 a02 = *(const uint2*)&sAr[r][cb];
                uint2 a13 = *(const uint2*)&sAr[r + 8][cb];
                uint2 b02 = *(const uint2*)&sAi[r][cb];
                uint2 b13 = *(const uint2*)&sAi[r + 8][cb];
                uint32 fa[4]  = {a02.x, a13.x, a02.y, a13.y};
                uint32 fb[4]  = {b02.x, b13.x, b02.y, b13.y};
                uint32 fbn[4] = {fb[0] ^ 0x80000000u, fb[1] ^ 0x80000000u,
                                 fb[2] ^ 0x80000000u, fb[3] ^ 0x80000000u};
                #pragma unroll
                for (int ni = 0; ni < 4; ni++) {
                    uint32 fwr[2] = {fwrv[ni].x, fwrv[ni].y};
                    uint32 fwi[2] = {fwiv[ni].x, fwiv[ni].y};
                    MMA_TF32(accR[mi][ni], fa,  fwr);
                    MMA_TF32(accR[mi][ni], fbn, fwi);
                    MMA_TF32(accI[mi][ni], fa,  fwi);
                    MMA_TF32(accI[mi][ni], fb,  fwr);
                }
            }
        }
        __syncthreads();
    }

    // epilogue: acc frag element (e0,e1)=row g, cols 2t,2t+1 ; (e2,e3)=row g+8
    #pragma unroll
    for (int ni = 0; ni < 4; ni++) {
        int n = n0 + wn * 32 + ni * 8 + 2 * t;
        float br0 = 0.f, br1 = 0.f, bi0 = 0.f, bi1 = 0.f;
        if (bm) {
            br0 = bm[n] * cosf(bp[n]);         bi0 = bm[n] * sinf(bp[n]);
            br1 = bm[n + 1] * cosf(bp[n + 1]); bi1 = bm[n + 1] * sinf(bp[n + 1]);
        }
        #pragma unroll
        for (int mi = 0; mi < 2; mi++) {
            int r = m0 + wm * 32 + mi * 16 + g;
            float* c0 = accR[mi][ni];
            float* c1 = accI[mi][ni];
            float2 o0 = make_float2(c0[0] + br0, c0[1] + br1);
            float2 o1 = make_float2(c0[2] + br0, c0[3] + br1);
            float2 o2 = make_float2(c1[0] + bi0, c1[1] + bi1);
            float2 o3 = make_float2(c1[2] + bi0, c1[3] + bi1);
            size_t i0 = (size_t)r * N + n;
            size_t i1 = (size_t)(r + 8) * N + n;
            if (mode == 1) {
                float2 x0 = *(const float2*)&Xr[i0], x1 = *(const float2*)&Xr[i1];
                float2 y0 = *(const float2*)&Xi[i0], y1 = *(const float2*)&Xi[i1];
                o0.x += x0.x; o0.y += x0.y; o1.x += x1.x; o1.y += x1.y;
                o2.x += y0.x; o2.y += y0.y; o3.x += y1.x; o3.y += y1.y;
            } else if (mode == 3) {
                float2 x0 = *(const float2*)&Cr[i0], x1 = *(const float2*)&Cr[i1];
                float2 y0 = *(const float2*)&Ci[i0], y1 = *(const float2*)&Ci[i1];
                o0.x += x0.x; o0.y += x0.y; o1.x += x1.x; o1.y += x1.y;
                o2.x += y0.x; o2.y += y0.y; o3.x += y1.x; o3.y += y1.y;
            }
            *(float2*)&Cr[i0] = o0;
            *(float2*)&Cr[i1] = o1;
            *(float2*)&Ci[i0] = o2;
            *(float2*)&Ci[i1] = o3;
        }
    }
}

// RoPE cos/sin table: 1024 positions x 32 freqs, computed in double once.
__global__ __launch_bounds__(256) void rope_tab_kernel(float2* __restrict__ tab) {
    int idx = blockIdx.x * 256 + threadIdx.x;   // < 32768
    int j = idx & 31, s = idx >> 5;
    double invf = pow(10000.0, -(double)(2 * j) / 64.0);
    double ang = (double)s * invf;
    double sd, cd;
    sincos(ang, &sd, &cd);
    tab[idx] = make_float2((float)cd, (float)sd);
}

// RoPE in place on q,k (real & imag) using the table.
__global__ __launch_bounds__(256) void rope_kernel(float* __restrict__ qr, float* __restrict__ qi,
                                                   float* __restrict__ kr, float* __restrict__ ki,
                                                   const float2* __restrict__ tab) {
    int idx = blockIdx.x * 256 + threadIdx.x;   // < B*H*S*32 = 1048576
    int j = idx & 31;
    int s = (idx >> 5) & 1023;
    int h = (idx >> 15) & 7;
    int b = idx >> 18;
    float2 cspair = tab[idx & 32767];
    float cs = cspair.x, sn = cspair.y;
    size_t base = (((size_t)b * SS + s) * DM) + h * HDD + j;
    float x0, x1;
    x0 = qr[base]; x1 = qr[base + 32]; qr[base] = x0 * cs - x1 * sn; qr[base + 32] = x1 * cs + x0 * sn;
    x0 = qi[base]; x1 = qi[base + 32]; qi[base] = x0 * cs - x1 * sn; qi[base + 32] = x1 * cs + x0 * sn;
    x0 = kr[base]; x1 = kr[base + 32]; kr[base] = x0 * cs - x1 * sn; kr[base + 32] = x1 * cs + x0 * sn;
    x0 = ki[base]; x1 = ki[base + 32]; ki[base] = x0 * cs - x1 * sn; ki[base + 32] = x1 * cs + x0 * sn;
}

// ============================================================================
// Fused flash attention (fp32, online softmax). One block per (bh, m-tile 64).
// Hermitian scores S = (qr.kr + qi.ki)/8, causal; O = softmax(S) @ (vr, vi).
// Block (16,16): thread owns 4(m) x 4 micro-tiles. Row stats via width-16
// shuffles (row group = 16 lanes of same ty within a warp).
// ============================================================================
__global__ __launch_bounds__(256) void flash_kernel(const float* __restrict__ qr,
                                                    const float* __restrict__ qi,
                                                    const float* __restrict__ kr,
                                                    const float* __restrict__ ki,
                                                    const float* __restrict__ vr,
                                                    const float* __restrict__ vi,
                                                    float* __restrict__ ar_out,
                                                    float* __restrict__ ai_out) {
    int bh = blockIdx.x, mt = blockIdx.y;
    int b = bh >> 3, h = bh & 7;
    __shared__ float sQr[16][64], sQi[16][64], sKr[16][64], sKi[16][64];
    __shared__ float sVr[16][64], sVi[16][64];
    __shared__ float sP[64][68];
    int tx = threadIdx.x, ty = threadIdx.y;
    int tid = ty * 16 + tx;
    int m0 = mt * 64;
    const size_t head = (size_t)b * SS * DM + (size_t)h * HDD;

    float Or[4][4] = {{0}}, Oi[4][4] = {{0}};
    float mrow[4], lrow[4];
    #pragma unroll
    for (int i = 0; i < 4; i++) { mrow[i] = -1e30f; lrow[i] = 0.f; }

    for (int nt = 0; nt <= mt; nt++) {
        int n0 = nt * 64;
        float S[4][4] = {{0}};
        // ---- scores: S += Q[m0 tile] . K[n0 tile]^T over HD=64 ----
        for (int k0 = 0; k0 < HDD; k0 += 16) {
            #pragma unroll
            for (int l = 0; l < 4; l++) {
                int idx = tid + l * 256;
                int r = idx >> 4, c = idx & 15;
                sQr[c][r] = qr[head + (size_t)(m0 + r) * DM + k0 + c];
                sQi[c][r] = qi[head + (size_t)(m0 + r) * DM + k0 + c];
                sKr[c][r] = kr[head + (size_t)(n0 + r) * DM + k0 + c];
                sKi[c][r] = ki[head + (size_t)(n0 + r) * DM + k0 + c];
            }
            __syncthreads();
            #pragma unroll
            for (int kk = 0; kk < 16; kk++) {
                float a[4], b2[4], c2[4], d2[4];
                #pragma unroll
                for (int j = 0; j < 4; j++) {
                    a[j]  = sQr[kk][ty * 4 + j];
                    b2[j] = sQi[kk][ty * 4 + j];
                    c2[j] = sKr[kk][tx * 4 + j];
                    d2[j] = sKi[kk][tx * 4 + j];
                }
                #pragma unroll
                for (int i2 = 0; i2 < 4; i2++)
                    #pragma unroll
                    for (int j2 = 0; j2 < 4; j2++) {
                        S[i2][j2] += a[i2] * c2[j2];
                        S[i2][j2] += b2[i2] * d2[j2];
                    }
            }
            __syncthreads();
        }
        // scale + causal mask (diagonal tile only)
        #pragma unroll
        for (int i = 0; i < 4; i++)
            #pragma unroll
            for (int j = 0; j < 4; j++) {
                S[i][j] *= 0.125f;
                if (nt == mt && (tx * 4 + j) > (ty * 4 + i)) S[i][j] = -1e30f;
            }
        // ---- online softmax ----
        #pragma unroll
        for (int i = 0; i < 4; i++) {
            float rm = fmaxf(fmaxf(S[i][0], S[i][1]), fmaxf(S[i][2], S[i][3]));
            #pragma unroll
            for (int w = 8; w > 0; w >>= 1)
                rm = fmaxf(rm, __shfl_xor_sync(0xffffffffu, rm, w));
            float newm = fmaxf(mrow[i], rm);
            float corr = __expf(mrow[i] - newm);
            float rs = 0.f;
            #pragma unroll
            for (int j = 0; j < 4; j++) { S[i][j] = __expf(S[i][j] - newm); rs += S[i][j]; }
            #pragma unroll
            for (int w = 8; w > 0; w >>= 1)
                rs += __shfl_xor_sync(0xffffffffu, rs, w);
            lrow[i] = lrow[i] * corr + rs;
            mrow[i] = newm;
            #pragma unroll
            for (int j = 0; j < 4; j++) { Or[i][j] *= corr; Oi[i][j] *= corr; }
        }
        // ---- stage P = S into SMEM (row-major [m][k]) ----
        #pragma unroll
        for (int i = 0; i < 4; i++)
            *(float4*)&sP[ty * 4 + i][tx * 4] = make_float4(S[i][0], S[i][1], S[i][2], S[i][3]);
        __syncthreads();
        // ---- O += P @ V (stream V in 16-deep chunks) ----
        for (int k0 = 0; k0 < 64; k0 += 16) {
            #pragma unroll
            for (int l = 0; l < 4; l++) {
                int idx = tid + l * 256;
                int kkk = idx >> 6, nn = idx & 63;
                sVr[kkk][nn] = vr[head + (size_t)(n0 + k0 + kkk) * DM + nn];
                sVi[kkk][nn] = vi[head + (size_t)(n0 + k0 + kkk) * DM + nn];
            }
            __syncthreads();
            #pragma unroll
            for (int kk = 0; kk < 16; kk++) {
                float pf[4], vrf[4], vif[4];
                #pragma unroll
                for (int i = 0; i < 4; i++) pf[i] = sP[ty * 4 + i][k0 + kk];
                #pragma unroll
                for (int j = 0; j < 4; j++) {
                    vrf[j] = sVr[kk][tx * 4 + j];
                    vif[j] = sVi[kk][tx * 4 + j];
                }
                #pragma unroll
                for (int i = 0; i < 4; i++)
                    #pragma unroll
                    for (int j = 0; j < 4; j++) {
                        Or[i][j] += pf[i] * vrf[j];
                        Oi[i][j] += pf[i] * vif[j];
                    }
            }
            __syncthreads();
        }
    }

    // ---- finalize: divide by l, write out ----
    #pragma unroll
    for (int i = 0; i < 4; i++) {
        float inv = 1.0f / lrow[i];
        size_t orow = head + (size_t)(m0 + ty * 4 + i) * DM + tx * 4;
        *(float4*)&ar_out[orow] = make_float4(Or[i][0] * inv, Or[i][1] * inv,
                                              Or[i][2] * inv, Or[i][3] * inv);
        *(float4*)&ai_out[orow] = make_float4(Oi[i][0] * inv, Oi[i][1] * inv,
                                              Oi[i][2] * inv, Oi[i][3] * inv);
    }
}

__global__ __launch_bounds__(256) void gateact_kernel(float* __restrict__ gr, float* __restrict__ gi,
                                                      const float* __restrict__ ur,
                                                      const float* __restrict__ ui) {
    size_t i = (size_t)blockIdx.x * 256 + threadIdx.x;
    float a = gr[i], b = gi[i];
    float mag = sqrtf(a * a + b * b);
    float s = 1.0f / (1.0f + expf(-mag));
    float gar = a * s, gai = b * s;
    float u = ur[i], v = ui[i];
    gr[i] = gar * u - gai * v;
    gi[i] = gar * v + gai * u;
}

// ---------------------------------------------------------------------------
extern "C" void kernel_launch(void* const* d_in, const int* in_sizes, int n_in,
                              void* d_out, int out_size) {
    const float* x_real = (const float*)d_in[0];
    const float* x_imag = (const float*)d_in[1];
    const float* ln1_gr = (const float*)d_in[2];
    const float* ln1_gi = (const float*)d_in[3];
    const float* ln1_br = (const float*)d_in[4];
    const float* ln1_bi = (const float*)d_in[5];
    const float* q_lm = (const float*)d_in[6];
    const float* q_ph = (const float*)d_in[7];
    const float* q_bm = (const float*)d_in[8];
    const float* q_bp = (const float*)d_in[9];
    const float* k_lm = (const float*)d_in[10];
    const float* k_ph = (const float*)d_in[11];
    const float* k_bm = (const float*)d_in[12];
    const float* k_bp = (const float*)d_in[13];
    const float* v_lm = (const float*)d_in[14];
    const float* v_ph = (const float*)d_in[15];
    const float* v_bm = (const float*)d_in[16];
    const float* v_bp = (const float*)d_in[17];
    const float* o_lm = (const float*)d_in[18];
    const float* o_ph = (const float*)d_in[19];
    const float* o_bm = (const float*)d_in[20];
    const float* o_bp = (const float*)d_in[21];
    const float* ln2_gr = (const float*)d_in[22];
    const float* ln2_gi = (const float*)d_in[23];
    const float* ln2_br = (const float*)d_in[24];
    const float* ln2_bi = (const float*)d_in[25];
    const float* gate_lm = (const float*)d_in[26];
    const float* gate_ph = (const float*)d_in[27];
    const float* up_lm = (const float*)d_in[28];
    const float* up_ph = (const float*)d_in[29];
    const float* down_lm = (const float*)d_in[30];
    const float* down_ph = (const float*)d_in[31];
    float* out = (float*)d_out;

    float* Sp = nullptr;
    cudaGetSymbolAddress((void**)&Sp, g_scratch);

    // scratch layout
    float* qwr = Sp;            // + q/k/v/o wr|wi pairs (8*DDE total)
    float* owr = Sp + 6 * DDE;  float* owi = owr + DDE;
    float* gwr = Sp + 8 * DDE;  // + gate/up/down wr|wi pairs (6*GDE)
    float* dwr = gwr + 4 * GDE; float* dwi = dwr + GDE;
    float* hr = gwr + 6 * GDE;  float* hi = hr + NDE;
    float* qr = hi + NDE;       float* qi = qr + NDE;
    float* kr = qi + NDE;       float* ki = kr + NDE;
    float* vr = ki + NDE;       float* vi = vr + NDE;
    float* ar = vi + NDE;       float* ai = ar + NDE;
    float* gr = ai + NDE;       float* gi = gr + NHE;
    float* ur = gi + NHE;       float* ui = ur + NHE;
    float* sc = ui + NHE;       // rope table lives here now

    // 1) materialize all weights in one launch
    make_w_all_kernel<<<(int)((4 * DDE + 3 * GDE) / 256), 256>>>(Sp,
        q_lm, q_ph, k_lm, k_ph, v_lm, v_ph, o_lm, o_ph,
        gate_lm, gate_ph, up_lm, up_ph, down_lm, down_ph);

    // 2) LN1
    cln_kernel<<<NT, 256>>>(x_real, x_imag, ln1_gr, ln1_gi, ln1_br, ln1_bi, hr, hi);

    // 3) QKV projections — ONE batched launch (z selects weight/output/bias)
    cgemm_tc_kernel<<<dim3(DM / 64, NT / 128, 3), 256>>>(
        hr, hi, qwr, 2 * DDE, DDE, qr, 2 * NDE, NDE,
        q_bm, q_bp, k_bm, k_bp, v_bm, v_bp, nullptr, nullptr, 0, NT, DM, DM);

    // 4) RoPE (table + apply)
    rope_tab_kernel<<<128, 256>>>((float2*)sc);
    rope_kernel<<<(BB * HH * SS * (HDD / 2)) / 256, 256>>>(qr, qi, kr, ki, (const float2*)sc);

    // 5) fused flash attention (exact fp32, online softmax)
    flash_kernel<<<dim3(BB * HH, SS / 64), dim3(16, 16)>>>(qr, qi, kr, ki, vr, vi, ar, ai);

    // 6) output projection with fused residual -> d_out directly (mode 1)
    cgemm_tc_kernel<<<dim3(DM / 64, NT / 128, 1), 256>>>(
        ar, ai, owr, 0, DDE, out, 0, NDE,
        o_bm, o_bp, nullptr, nullptr, nullptr, nullptr, x_real, x_imag, 1, NT, DM, DM);

    // 7) LN2 (reads residual from d_out)
    cln_kernel<<<NT, 256>>>(out, out + NDE, ln2_gr, ln2_gi, ln2_br, ln2_bi, hr, hi);

    // 8) FFN gate+up — ONE batched launch
    cgemm_tc_kernel<<<dim3(HIDD / 64, NT / 128, 2), 256>>>(
        hr, hi, gwr, 2 * GDE, GDE, gr, 2 * NHE, NHE,
        nullptr, nullptr, nullptr, nullptr, nullptr, nullptr, nullptr, nullptr, 0, NT, HIDD, DM);
    gateact_kernel<<<(int)(NHE / 256), 256>>>(gr, gi, ur, ui);

    // 9) down proj with fused accumulate into d_out (mode 3)
    cgemm_tc_kernel<<<dim3(DM / 64, NT / 128, 1), 256>>>(
        gr, gi, dwr, 0, GDE, out, 0, NDE,
        nullptr, nullptr, nullptr, nullptr, nullptr, nullptr, nullptr, nullptr, 3, NT, DM, HIDD);
}

// round 15
// speedup vs baseline: 1.0348x; 1.0348x over previous
#include <cuda_runtime.h>
#include <math.h>

// Problem dims (fixed)
#define BB 4
#define SS 1024
#define DM 512
#define HH 8
#define HDD 64
#define HIDD 2048
#define NT (BB*SS)                 // 4096 token rows
#define NDE ((size_t)NT*DM)        // 2097152
#define NHE ((size_t)NT*HIDD)      // 8388608
#define DDE ((size_t)DM*DM)        // 262144
#define GDE ((size_t)HIDD*DM)      // 1048576

typedef unsigned long long ull;
typedef unsigned int uint32;

// -------- scratch: one big __device__ array (no allocations allowed) --------
__device__ float g_scratch[96468992];

// ---- tf32 helpers ----
__device__ __forceinline__ uint32 to_tf32(float x) {
    uint32 r; asm("cvt.rna.tf32.f32 %0, %1;" : "=r"(r) : "f"(x)); return r;
}
#define MMA_TF32(d, a, b) \
    asm volatile("mma.sync.aligned.m16n8k8.row.col.f32.tf32.tf32.f32 " \
                 "{%0,%1,%2,%3}, {%4,%5,%6,%7}, {%8,%9}, {%0,%1,%2,%3};" \
                 : "+f"(d[0]), "+f"(d[1]), "+f"(d[2]), "+f"(d[3]) \
                 : "r"(a[0]), "r"(a[1]), "r"(a[2]), "r"(a[3]), "r"(b[0]), "r"(b[1]))

// ---------------------------------------------------------------------------
// all 7 magnitude/phase weight materializations in ONE launch
__global__ __launch_bounds__(256) void make_w_all_kernel(float* __restrict__ Sp,
    const float* __restrict__ q_lm, const float* __restrict__ q_ph,
    const float* __restrict__ k_lm, const float* __restrict__ k_ph,
    const float* __restrict__ v_lm, const float* __restrict__ v_ph,
    const float* __restrict__ o_lm, const float* __restrict__ o_ph,
    const float* __restrict__ g_lm, const float* __restrict__ g_ph,
    const float* __restrict__ u_lm, const float* __restrict__ u_ph,
    const float* __restrict__ d_lm, const float* __restrict__ d_ph) {
    int i = blockIdx.x * 256 + threadIdx.x;     // < 4*DDE + 3*GDE = 4194304
    const float *lm, *ph;
    float *wr, *wi;
    int off;
    if (i < (int)(4 * DDE)) {
        int w = i / (int)DDE; off = i - w * (int)DDE;
        lm = (w == 0) ? q_lm : (w == 1) ? k_lm : (w == 2) ? v_lm : o_lm;
        ph = (w == 0) ? q_ph : (w == 1) ? k_ph : (w == 2) ? v_ph : o_ph;
        wr = Sp + (size_t)w * 2 * DDE + off; wi = wr + DDE;
    } else {
        int j = i - (int)(4 * DDE);
        int w = j / (int)GDE; off = j - w * (int)GDE;
        lm = (w == 0) ? g_lm : (w == 1) ? u_lm : d_lm;
        ph = (w == 0) ? g_ph : (w == 1) ? u_ph : d_ph;
        wr = Sp + 8 * DDE + (size_t)w * 2 * GDE + off; wi = wr + GDE;
    }
    float m = expf(lm[off]);
    float p = ph[off];
    *wr = m * cosf(p);
    *wi = m * sinf(p);
}

// complex layernorm over last dim D=512; one block per row, 256 threads
__global__ __launch_bounds__(256) void cln_kernel(const float* __restrict__ xr,
                                                  const float* __restrict__ xi,
                                                  const float* __restrict__ gr,
                                                  const float* __restrict__ gi,
                                                  const float* __restrict__ br,
                                                  const float* __restrict__ bi,
                                                  float* __restrict__ outr,
                                                  float* __restrict__ outi) {
    int row = blockIdx.x;
    int t = threadIdx.x;
    const float* xrp = xr + (size_t)row * DM;
    const float* xip = xi + (size_t)row * DM;
    float a0 = xrp[t], a1 = xrp[t + 256];
    float b0 = xip[t], b1 = xip[t + 256];
    __shared__ float red[256];

    red[t] = a0 + a1; __syncthreads();
    for (int s2 = 128; s2 > 0; s2 >>= 1) { if (t < s2) red[t] += red[t + s2]; __syncthreads(); }
    float mr = red[0] * (1.0f / DM); __syncthreads();

    red[t] = b0 + b1; __syncthreads();
    for (int s2 = 128; s2 > 0; s2 >>= 1) { if (t < s2) red[t] += red[t + s2]; __syncthreads(); }
    float mi = red[0] * (1.0f / DM); __syncthreads();

    float c0 = a0 - mr, c1 = a1 - mr, d0 = b0 - mi, d1 = b1 - mi;
    red[t] = c0 * c0 + c1 * c1 + d0 * d0 + d1 * d1; __syncthreads();
    for (int s2 = 128; s2 > 0; s2 >>= 1) { if (t < s2) red[t] += red[t + s2]; __syncthreads(); }
    float inv = rsqrtf(red[0] * (1.0f / DM) + 1e-6f);

    float* orow = outr + (size_t)row * DM;
    float* oirow = outi + (size_t)row * DM;
    {
        float nr = c0 * inv, ni = d0 * inv;
        orow[t]  = nr * gr[t] - ni * gi[t] + br[t];
        oirow[t] = nr * gi[t] + ni * gr[t] + bi[t];
    }
    {
        int d_ = t + 256;
        float nr = c1 * inv, ni = d1 * inv;
        orow[d_]  = nr * gr[d_] - ni * gi[d_] + br[d_];
        oirow[d_] = nr * gi[d_] + ni * gr[d_] + bi[d_];
    }
}

// ============================================================================
// Tensor-core complex GEMM (tf32 mma.sync m16n8k8), batched over blockIdx.z.
// SMEM k-columns PERMUTED so each mma fragment pair (c, c+4) is adjacent
// -> all fragment gathers become conflict-free LDS.64 (row pad 24 words).
// mode 0: write acc+bias. mode 1: +X (fused residual). mode 3: += C.
// ============================================================================
__global__ __launch_bounds__(256, 2) void cgemm_tc_kernel(
    const float* __restrict__ Ar, const float* __restrict__ Ai,
    const float* __restrict__ Wbase, size_t wzs, size_t wioff,
    float* __restrict__ Cbase, size_t czs, size_t cioff,
    const float* __restrict__ bm0, const float* __restrict__ bp0,
    const float* __restrict__ bm1, const float* __restrict__ bp1,
    const float* __restrict__ bm2, const float* __restrict__ bp2,
    const float* __restrict__ Xr, const float* __restrict__ Xi,
    int mode, int M, int N, int K) {
    __shared__ uint32 sAr[128][24], sAi[128][24];
    __shared__ uint32 sWr[64][24],  sWi[64][24];

    int zz = blockIdx.z;
    const float* Wr = Wbase + (size_t)zz * wzs;
    const float* Wi = Wr + wioff;
    float* Cr = Cbase + (size_t)zz * czs;
    float* Ci = Cr + cioff;
    const float* bm = (zz == 0) ? bm0 : (zz == 1) ? bm1 : bm2;
    const float* bp = (zz == 0) ? bp0 : (zz == 1) ? bp1 : bp2;

    int m0 = blockIdx.y * 128, n0 = blockIdx.x * 64;
    int tid = threadIdx.x;
    int warp = tid >> 5, lane = tid & 31;
    int wm = warp & 3, wn = warp >> 2;
    int g = lane >> 2, t = lane & 3;

    // fill assignments
    int rA = tid >> 1;                 // 0..127
    int hA = tid & 1;                  // k-half (8 cols)
    int rW = tid >> 2;                 // 0..63
    int selW = (tid >> 1) & 1;         // 0=Wr, 1=Wi
    int hW = tid & 1;

    float accR[2][4][4], accI[2][4][4];
    #pragma unroll
    for (int mi = 0; mi < 2; mi++)
        #pragma unroll
        for (int ni = 0; ni < 4; ni++)
            #pragma unroll
            for (int e = 0; e < 4; e++) { accR[mi][ni][e] = 0.f; accI[mi][ni][e] = 0.f; }

    for (int k0 = 0; k0 < K; k0 += 16) {
        // ---- fill A (both r and i) with permuted columns ----
        {
            const float* arow = Ar + (size_t)(m0 + rA) * K + k0 + hA * 8;
            const float* brow = Ai + (size_t)(m0 + rA) * K + k0 + hA * 8;
            float4 va = *(const float4*)arow;        // cols +0..3
            float4 vb = *(const float4*)(arow + 4);  // cols +4..7
            uint32* dst = &sAr[rA][hA * 8];
            *(uint2*)(dst + 0) = make_uint2(to_tf32(va.x), to_tf32(vb.x));
            *(uint2*)(dst + 2) = make_uint2(to_tf32(va.y), to_tf32(vb.y));
            *(uint2*)(dst + 4) = make_uint2(to_tf32(va.z), to_tf32(vb.z));
            *(uint2*)(dst + 6) = make_uint2(to_tf32(va.w), to_tf32(vb.w));
            float4 vc = *(const float4*)brow;
            float4 vd = *(const float4*)(brow + 4);
            uint32* dsi = &sAi[rA][hA * 8];
            *(uint2*)(dsi + 0) = make_uint2(to_tf32(vc.x), to_tf32(vd.x));
            *(uint2*)(dsi + 2) = make_uint2(to_tf32(vc.y), to_tf32(vd.y));
            *(uint2*)(dsi + 4) = make_uint2(to_tf32(vc.z), to_tf32(vd.z));
            *(uint2*)(dsi + 6) = make_uint2(to_tf32(vc.w), to_tf32(vd.w));
        }
        // ---- fill W (r or i selected per thread) ----
        {
            const float* wsrc = (selW ? Wi : Wr) + (size_t)(n0 + rW) * K + k0 + hW * 8;
            float4 va = *(const float4*)wsrc;
            float4 vb = *(const float4*)(wsrc + 4);
            uint32* dst = (selW ? &sWi[rW][hW * 8] : &sWr[rW][hW * 8]);
            *(uint2*)(dst + 0) = make_uint2(to_tf32(va.x), to_tf32(vb.x));
            *(uint2*)(dst + 2) = make_uint2(to_tf32(va.y), to_tf32(vb.y));
            *(uint2*)(dst + 4) = make_uint2(to_tf32(va.z), to_tf32(vb.z));
            *(uint2*)(dst + 6) = make_uint2(to_tf32(va.w), to_tf32(vb.w));
        }
        __syncthreads();

        #pragma unroll
        for (int kk = 0; kk < 16; kk += 8) {
            int cb = (kk >> 3) * 8 + t * 2;
            uint2 fwrv[4], fwiv[4];
            #pragma unroll
            for (int ni = 0; ni < 4; ni++) {
                int n = wn * 32 + ni * 8 + g;
                fwrv[ni] = *(const uint2*)&sWr[n][cb];
                fwiv[ni] = *(const uint2*)&sWi[n][cb];
            }
            #pragma unroll
            for (int mi = 0; mi < 2; mi++) {
                int r = wm * 32 + mi * 16 + g;
                uint2 a02 = *(const uint2*)&sAr[r][cb];
                uint2 a13 = *(const uint2*)&sAr[r + 8][cb];
                uint2 b02 = *(const uint2*)&sAi[r][cb];
                uint2 b13 = *(const uint2*)&sAi[r + 8][cb];
                uint32 fa[4]  = {a02.x, a13.x, a02.y, a13.y};
                uint32 fb[4]  = {b02.x, b13.x, b02.y, b13.y};
                uint32 fbn[4] = {fb[0] ^ 0x80000000u, fb[1] ^ 0x80000000u,
                                 fb[2] ^ 0x80000000u, fb[3] ^ 0x80000000u};
                #pragma unroll
                for (int ni = 0; ni < 4; ni++) {
                    uint32 fwr[2] = {fwrv[ni].x, fwrv[ni].y};
                    uint32 fwi[2] = {fwiv[ni].x, fwiv[ni].y};
                    MMA_TF32(accR[mi][ni], fa,  fwr);
                    MMA_TF32(accR[mi][ni], fbn, fwi);
                    MMA_TF32(accI[mi][ni], fa,  fwi);
                    MMA_TF32(accI[mi][ni], fb,  fwr);
                }
            }
        }
        __syncthreads();
    }

    // epilogue: acc frag element (e0,e1)=row g, cols 2t,2t+1 ; (e2,e3)=row g+8
    #pragma unroll
    for (int ni = 0; ni < 4; ni++) {
        int n = n0 + wn * 32 + ni * 8 + 2 * t;
        float br0 = 0.f, br1 = 0.f, bi0 = 0.f, bi1 = 0.f;
        if (bm) {
            br0 = bm[n] * cosf(bp[n]);         bi0 = bm[n] * sinf(bp[n]);
            br1 = bm[n + 1] * cosf(bp[n + 1]); bi1 = bm[n + 1] * sinf(bp[n + 1]);
        }
        #pragma unroll
        for (int mi = 0; mi < 2; mi++) {
            int r = m0 + wm * 32 + mi * 16 + g;
            float* c0 = accR[mi][ni];
            float* c1 = accI[mi][ni];
            float2 o0 = make_float2(c0[0] + br0, c0[1] + br1);
            float2 o1 = make_float2(c0[2] + br0, c0[3] + br1);
            float2 o2 = make_float2(c1[0] + bi0, c1[1] + bi1);
            float2 o3 = make_float2(c1[2] + bi0, c1[3] + bi1);
            size_t i0 = (size_t)r * N + n;
            size_t i1 = (size_t)(r + 8) * N + n;
            if (mode == 1) {
                float2 x0 = *(const float2*)&Xr[i0], x1 = *(const float2*)&Xr[i1];
                float2 y0 = *(const float2*)&Xi[i0], y1 = *(const float2*)&Xi[i1];
                o0.x += x0.x; o0.y += x0.y; o1.x += x1.x; o1.y += x1.y;
                o2.x += y0.x; o2.y += y0.y; o3.x += y1.x; o3.y += y1.y;
            } else if (mode == 3) {
                float2 x0 = *(const float2*)&Cr[i0], x1 = *(const float2*)&Cr[i1];
                float2 y0 = *(const float2*)&Ci[i0], y1 = *(const float2*)&Ci[i1];
                o0.x += x0.x; o0.y += x0.y; o1.x += x1.x; o1.y += x1.y;
                o2.x += y0.x; o2.y += y0.y; o3.x += y1.x; o3.y += y1.y;
            }
            *(float2*)&Cr[i0] = o0;
            *(float2*)&Cr[i1] = o1;
            *(float2*)&Ci[i0] = o2;
            *(float2*)&Ci[i1] = o3;
        }
    }
}

// RoPE cos/sin table: 1024 positions x 32 freqs, computed in double once.
__global__ __launch_bounds__(256) void rope_tab_kernel(float2* __restrict__ tab) {
    int idx = blockIdx.x * 256 + threadIdx.x;   // < 32768
    int j = idx & 31, s = idx >> 5;
    double invf = pow(10000.0, -(double)(2 * j) / 64.0);
    double ang = (double)s * invf;
    double sd, cd;
    sincos(ang, &sd, &cd);
    tab[idx] = make_float2((float)cd, (float)sd);
}

// RoPE in place on q,k (real & imag) using the table.
__global__ __launch_bounds__(256) void rope_kernel(float* __restrict__ qr, float* __restrict__ qi,
                                                   float* __restrict__ kr, float* __restrict__ ki,
                                                   const float2* __restrict__ tab) {
    int idx = blockIdx.x * 256 + threadIdx.x;   // < B*H*S*32 = 1048576
    int j = idx & 31;
    int s = (idx >> 5) & 1023;
    int h = (idx >> 15) & 7;
    int b = idx >> 18;
    float2 cspair = tab[idx & 32767];
    float cs = cspair.x, sn = cspair.y;
    size_t base = (((size_t)b * SS + s) * DM) + h * HDD + j;
    float x0, x1;
    x0 = qr[base]; x1 = qr[base + 32]; qr[base] = x0 * cs - x1 * sn; qr[base + 32] = x1 * cs + x0 * sn;
    x0 = qi[base]; x1 = qi[base + 32]; qi[base] = x0 * cs - x1 * sn; qi[base + 32] = x1 * cs + x0 * sn;
    x0 = kr[base]; x1 = kr[base + 32]; kr[base] = x0 * cs - x1 * sn; kr[base + 32] = x1 * cs + x0 * sn;
    x0 = ki[base]; x1 = ki[base + 32]; ki[base] = x0 * cs - x1 * sn; ki[base + 32] = x1 * cs + x0 * sn;
}

// ============================================================================
// Fused flash attention (fp32, online softmax), WAVE-BALANCED:
// grid (32 bh, 8 slots); slot s processes m-tiles {s, 15-s} back to back
// -> every block does exactly 17 KV-tile iterations; 256 blocks = 1 wave.
// ============================================================================
struct FlashSmem {
    float sQr[16][64], sQi[16][64], sKr[16][64], sKi[16][64];
    float sVr[16][64], sVi[16][64];
    float sP[64][68];
};

__device__ __forceinline__ void flash_one(int bh, int mt, FlashSmem& fs,
                                          const float* __restrict__ qr,
                                          const float* __restrict__ qi,
                                          const float* __restrict__ kr,
                                          const float* __restrict__ ki,
                                          const float* __restrict__ vr,
                                          const float* __restrict__ vi,
                                          float* __restrict__ ar_out,
                                          float* __restrict__ ai_out) {
    int b = bh >> 3, h = bh & 7;
    int tx = threadIdx.x, ty = threadIdx.y;
    int tid = ty * 16 + tx;
    int m0 = mt * 64;
    const size_t head = (size_t)b * SS * DM + (size_t)h * HDD;

    float Or[4][4] = {{0}}, Oi[4][4] = {{0}};
    float mrow[4], lrow[4];
    #pragma unroll
    for (int i = 0; i < 4; i++) { mrow[i] = -1e30f; lrow[i] = 0.f; }

    for (int nt = 0; nt <= mt; nt++) {
        int n0 = nt * 64;
        float S[4][4] = {{0}};
        // ---- scores: S += Q[m0 tile] . K[n0 tile]^T over HD=64 ----
        for (int k0 = 0; k0 < HDD; k0 += 16) {
            #pragma unroll
            for (int l = 0; l < 4; l++) {
                int idx = tid + l * 256;
                int r = idx >> 4, c = idx & 15;
                fs.sQr[c][r] = qr[head + (size_t)(m0 + r) * DM + k0 + c];
                fs.sQi[c][r] = qi[head + (size_t)(m0 + r) * DM + k0 + c];
                fs.sKr[c][r] = kr[head + (size_t)(n0 + r) * DM + k0 + c];
                fs.sKi[c][r] = ki[head + (size_t)(n0 + r) * DM + k0 + c];
            }
            __syncthreads();
            #pragma unroll
            for (int kk = 0; kk < 16; kk++) {
                float a[4], b2[4], c2[4], d2[4];
                #pragma unroll
                for (int j = 0; j < 4; j++) {
                    a[j]  = fs.sQr[kk][ty * 4 + j];
                    b2[j] = fs.sQi[kk][ty * 4 + j];
                    c2[j] = fs.sKr[kk][tx * 4 + j];
                    d2[j] = fs.sKi[kk][tx * 4 + j];
                }
                #pragma unroll
                for (int i2 = 0; i2 < 4; i2++)
                    #pragma unroll
                    for (int j2 = 0; j2 < 4; j2++) {
                        S[i2][j2] += a[i2] * c2[j2];
                        S[i2][j2] += b2[i2] * d2[j2];
                    }
            }
            __syncthreads();
        }
        // scale + causal mask (diagonal tile only)
        #pragma unroll
        for (int i = 0; i < 4; i++)
            #pragma unroll
            for (int j = 0; j < 4; j++) {
                S[i][j] *= 0.125f;
                if (nt == mt && (tx * 4 + j) > (ty * 4 + i)) S[i][j] = -1e30f;
            }
        // ---- online softmax ----
        #pragma unroll
        for (int i = 0; i < 4; i++) {
            float rm = fmaxf(fmaxf(S[i][0], S[i][1]), fmaxf(S[i][2], S[i][3]));
            #pragma unroll
            for (int w = 8; w > 0; w >>= 1)
                rm = fmaxf(rm, __shfl_xor_sync(0xffffffffu, rm, w));
            float newm = fmaxf(mrow[i], rm);
            float corr = __expf(mrow[i] - newm);
            float rs = 0.f;
            #pragma unroll
            for (int j = 0; j < 4; j++) { S[i][j] = __expf(S[i][j] - newm); rs += S[i][j]; }
            #pragma unroll
            for (int w = 8; w > 0; w >>= 1)
                rs += __shfl_xor_sync(0xffffffffu, rs, w);
            lrow[i] = lrow[i] * corr + rs;
            mrow[i] = newm;
            #pragma unroll
            for (int j = 0; j < 4; j++) { Or[i][j] *= corr; Oi[i][j] *= corr; }
        }
        // ---- stage P = S into SMEM (row-major [m][k]) ----
        #pragma unroll
        for (int i = 0; i < 4; i++)
            *(float4*)&fs.sP[ty * 4 + i][tx * 4] = make_float4(S[i][0], S[i][1], S[i][2], S[i][3]);
        __syncthreads();
        // ---- O += P @ V (stream V in 16-deep chunks) ----
        for (int k0 = 0; k0 < 64; k0 += 16) {
            #pragma unroll
            for (int l = 0; l < 4; l++) {
                int idx = tid + l * 256;
                int kkk = idx >> 6, nn = idx & 63;
                fs.sVr[kkk][nn] = vr[head + (size_t)(n0 + k0 + kkk) * DM + nn];
                fs.sVi[kkk][nn] = vi[head + (size_t)(n0 + k0 + kkk) * DM + nn];
            }
            __syncthreads();
            #pragma unroll
            for (int kk = 0; kk < 16; kk++) {
                float pf[4], vrf[4], vif[4];
                #pragma unroll
                for (int i = 0; i < 4; i++) pf[i] = fs.sP[ty * 4 + i][k0 + kk];
                #pragma unroll
                for (int j = 0; j < 4; j++) {
                    vrf[j] = fs.sVr[kk][tx * 4 + j];
                    vif[j] = fs.sVi[kk][tx * 4 + j];
                }
                #pragma unroll
                for (int i = 0; i < 4; i++)
                    #pragma unroll
                    for (int j = 0; j < 4; j++) {
                        Or[i][j] += pf[i] * vrf[j];
                        Oi[i][j] += pf[i] * vif[j];
                    }
            }
            __syncthreads();
        }
    }

    // ---- finalize: divide by l, write out (registers only; SMEM already
    // fenced by the last __syncthreads of the AV loop) ----
    #pragma unroll
    for (int i = 0; i < 4; i++) {
        float inv = 1.0f / lrow[i];
        size_t orow = head + (size_t)(m0 + ty * 4 + i) * DM + tx * 4;
        *(float4*)&ar_out[orow] = make_float4(Or[i][0] * inv, Or[i][1] * inv,
                                              Or[i][2] * inv, Or[i][3] * inv);
        *(float4*)&ai_out[orow] = make_float4(Oi[i][0] * inv, Oi[i][1] * inv,
                                              Oi[i][2] * inv, Oi[i][3] * inv);
    }
}

__global__ __launch_bounds__(256) void flash_kernel(const float* __restrict__ qr,
                                                    const float* __restrict__ qi,
                                                    const float* __restrict__ kr,
                                                    const float* __restrict__ ki,
                                                    const float* __restrict__ vr,
                                                    const float* __restrict__ vi,
                                                    float* __restrict__ ar_out,
                                                    float* __restrict__ ai_out) {
    __shared__ FlashSmem fs;
    int bh = blockIdx.x;
    int slot = blockIdx.y;              // 0..7
    flash_one(bh, slot, fs, qr, qi, kr, ki, vr, vi, ar_out, ai_out);
    __syncthreads();
    flash_one(bh, 15 - slot, fs, qr, qi, kr, ki, vr, vi, ar_out, ai_out);
}

__global__ __launch_bounds__(256) void gateact_kernel(float* __restrict__ gr, float* __restrict__ gi,
                                                      const float* __restrict__ ur,
                                                      const float* __restrict__ ui) {
    size_t i = (size_t)blockIdx.x * 256 + threadIdx.x;
    float a = gr[i], b = gi[i];
    float mag = sqrtf(a * a + b * b);
    float s = 1.0f / (1.0f + expf(-mag));
    float gar = a * s, gai = b * s;
    float u = ur[i], v = ui[i];
    gr[i] = gar * u - gai * v;
    gi[i] = gar * v + gai * u;
}

// ---------------------------------------------------------------------------
extern "C" void kernel_launch(void* const* d_in, const int* in_sizes, int n_in,
                              void* d_out, int out_size) {
    const float* x_real = (const float*)d_in[0];
    const float* x_imag = (const float*)d_in[1];
    const float* ln1_gr = (const float*)d_in[2];
    const float* ln1_gi = (const float*)d_in[3];
    const float* ln1_br = (const float*)d_in[4];
    const float* ln1_bi = (const float*)d_in[5];
    const float* q_lm = (const float*)d_in[6];
    const float* q_ph = (const float*)d_in[7];
    const float* q_bm = (const float*)d_in[8];
    const float* q_bp = (const float*)d_in[9];
    const float* k_lm = (const float*)d_in[10];
    const float* k_ph = (const float*)d_in[11];
    const float* k_bm = (const float*)d_in[12];
    const float* k_bp = (const float*)d_in[13];
    const float* v_lm = (const float*)d_in[14];
    const float* v_ph = (const float*)d_in[15];
    const float* v_bm = (const float*)d_in[16];
    const float* v_bp = (const float*)d_in[17];
    const float* o_lm = (const float*)d_in[18];
    const float* o_ph = (const float*)d_in[19];
    const float* o_bm = (const float*)d_in[20];
    const float* o_bp = (const float*)d_in[21];
    const float* ln2_gr = (const float*)d_in[22];
    const float* ln2_gi = (const float*)d_in[23];
    const float* ln2_br = (const float*)d_in[24];
    const float* ln2_bi = (const float*)d_in[25];
    const float* gate_lm = (const float*)d_in[26];
    const float* gate_ph = (const float*)d_in[27];
    const float* up_lm = (const float*)d_in[28];
    const float* up_ph = (const float*)d_in[29];
    const float* down_lm = (const float*)d_in[30];
    const float* down_ph = (const float*)d_in[31];
    float* out = (float*)d_out;

    float* Sp = nullptr;
    cudaGetSymbolAddress((void**)&Sp, g_scratch);

    // scratch layout
    float* qwr = Sp;            // + q/k/v/o wr|wi pairs (8*DDE total)
    float* owr = Sp + 6 * DDE;  float* owi = owr + DDE;
    float* gwr = Sp + 8 * DDE;  // + gate/up/down wr|wi pairs (6*GDE)
    float* dwr = gwr + 4 * GDE; float* dwi = dwr + GDE;
    float* hr = gwr + 6 * GDE;  float* hi = hr + NDE;
    float* qr = hi + NDE;       float* qi = qr + NDE;
    float* kr = qi + NDE;       float* ki = kr + NDE;
    float* vr = ki + NDE;       float* vi = vr + NDE;
    float* ar = vi + NDE;       float* ai = ar + NDE;
    float* gr = ai + NDE;       float* gi = gr + NHE;
    float* ur = gi + NHE;       float* ui = ur + NHE;
    float* sc = ui + NHE;       // rope table lives here

    // 1) materialize all weights in one launch
    make_w_all_kernel<<<(int)((4 * DDE + 3 * GDE) / 256), 256>>>(Sp,
        q_lm, q_ph, k_lm, k_ph, v_lm, v_ph, o_lm, o_ph,
        gate_lm, gate_ph, up_lm, up_ph, down_lm, down_ph);

    // 2) LN1
    cln_kernel<<<NT, 256>>>(x_real, x_imag, ln1_gr, ln1_gi, ln1_br, ln1_bi, hr, hi);

    // 3) QKV projections — ONE batched launch (z selects weight/output/bias)
    cgemm_tc_kernel<<<dim3(DM / 64, NT / 128, 3), 256>>>(
        hr, hi, qwr, 2 * DDE, DDE, qr, 2 * NDE, NDE,
        q_bm, q_bp, k_bm, k_bp, v_bm, v_bp, nullptr, nullptr, 0, NT, DM, DM);

    // 4) RoPE (table + apply)
    rope_tab_kernel<<<128, 256>>>((float2*)sc);
    rope_kernel<<<(BB * HH * SS * (HDD / 2)) / 256, 256>>>(qr, qi, kr, ki, (const float2*)sc);

    // 5) fused flash attention — wave-balanced (pairing mt with 15-mt)
    flash_kernel<<<dim3(BB * HH, SS / 128), dim3(16, 16)>>>(qr, qi, kr, ki, vr, vi, ar, ai);

    // 6) output projection with fused residual -> d_out directly (mode 1)
    cgemm_tc_kernel<<<dim3(DM / 64, NT / 128, 1), 256>>>(
        ar, ai, owr, 0, DDE, out, 0, NDE,
        o_bm, o_bp, nullptr, nullptr, nullptr, nullptr, x_real, x_imag, 1, NT, DM, DM);

    // 7) LN2 (reads residual from d_out)
    cln_kernel<<<NT, 256>>>(out, out + NDE, ln2_gr, ln2_gi, ln2_br, ln2_bi, hr, hi);

    // 8) FFN gate+up — ONE batched launch
    cgemm_tc_kernel<<<dim3(HIDD / 64, NT / 128, 2), 256>>>(
        hr, hi, gwr, 2 * GDE, GDE, gr, 2 * NHE, NHE,
        nullptr, nullptr, nullptr, nullptr, nullptr, nullptr, nullptr, nullptr, 0, NT, HIDD, DM);
    gateact_kernel<<<(int)(NHE / 256), 256>>>(gr, gi, ur, ui);

    // 9) down proj with fused accumulate into d_out (mode 3)
    cgemm_tc_kernel<<<dim3(DM / 64, NT / 128, 1), 256>>>(
        gr, gi, dwr, 0, GDE, out, 0, NDE,
        nullptr, nullptr, nullptr, nullptr, nullptr, nullptr, nullptr, nullptr, 3, NT, DM, HIDD);
}